// round 1
// baseline (speedup 1.0000x reference)
#include <cuda_runtime.h>

#define Fdim 60
#define Mdim 600
#define Cdim 8
#define OUTd 18
#define MT   120
#define NCH  5
#define MP   121      // padded m-stride for transposed x tile
#define NTHR 512

__global__ __launch_bounds__(NTHR, 2)
void netfv_kernel(const float* __restrict__ gx,     // [B*600, 60]
                  const float* __restrict__ gW,     // [60, 8]
                  const float* __restrict__ gcov,   // [60, 8]
                  const float* __restrict__ gbias,  // [8]
                  const float* __restrict__ gw2,    // [60, 8]
                  const float* __restrict__ gH,     // [960, 18]
                  float* __restrict__ gout)         // [B, 18]
{
    __shared__ __align__(16) float s_xT[Fdim * MP];   // 29 KB, reused as scratch later
    __shared__ __align__(16) float s_act[MT * Cdim];  // [m][c]
    __shared__ __align__(16) float s_W[Fdim * Cdim];
    __shared__ __align__(16) float s_asum[4 * 8];     // [part][c], then row0 = final
    __shared__ float s_bias[Cdim];
    __shared__ float s_q1[8];
    __shared__ float s_q2;
    __shared__ float s_rc[8];
    __shared__ float s_rg;
    __shared__ float s_sc2;

    const int tid = threadIdx.x;
    const int b = blockIdx.x;

    if (tid < Fdim * Cdim) s_W[tid] = gW[tid];
    if (tid < Cdim) s_bias[tid] = gbias[tid];
    if (tid < 8) s_q1[tid] = 0.f;
    if (tid == 8) s_q2 = 0.f;

    // Phase-B mapping: 480 threads own (g = m-group 0..7, f = 0..59)
    const int g = tid / Fdim;
    const int f = tid - g * Fdim;
    const bool fvthr = (tid < 480);

    float acc1[8], acc2[8];
#pragma unroll
    for (int c = 0; c < 8; c++) { acc1[c] = 0.f; acc2[c] = 0.f; }
    float asum_p = 0.f;                    // used by threads 480..511
    const int aj = tid - 480;
    const int acc_c = aj & 7;
    const int acc_p = aj >> 3;

    const float* xb = gx + (size_t)b * (Mdim * Fdim);

    for (int ch = 0; ch < NCH; ++ch) {
        __syncthreads();
        // ---- load chunk (coalesced global) into transposed smem tile ----
        const float* xc = xb + ch * (MT * Fdim);
#pragma unroll 4
        for (int idx = tid; idx < MT * Fdim; idx += NTHR) {
            int m = idx / Fdim;
            int k = idx - m * Fdim;
            s_xT[k * MP + m] = xc[idx];
        }
        __syncthreads();
        // ---- phase A: act = softmax(x @ W + bias), thread-per-row ----
        if (tid < MT) {
            float a[8];
#pragma unroll
            for (int c = 0; c < 8; c++) a[c] = s_bias[c];
#pragma unroll 4
            for (int k = 0; k < Fdim; k++) {
                float xk = s_xT[k * MP + tid];
                const float4* wv = (const float4*)&s_W[k * 8];
                float4 w0 = wv[0], w1 = wv[1];
                a[0] += xk * w0.x; a[1] += xk * w0.y;
                a[2] += xk * w0.z; a[3] += xk * w0.w;
                a[4] += xk * w1.x; a[5] += xk * w1.y;
                a[6] += xk * w1.z; a[7] += xk * w1.w;
            }
            float mx = a[0];
#pragma unroll
            for (int c = 1; c < 8; c++) mx = fmaxf(mx, a[c]);
            float s = 0.f;
#pragma unroll
            for (int c = 0; c < 8; c++) { a[c] = __expf(a[c] - mx); s += a[c]; }
            float inv = 1.f / s;
            float4* av = (float4*)&s_act[tid * 8];
            av[0] = make_float4(a[0]*inv, a[1]*inv, a[2]*inv, a[3]*inv);
            av[1] = make_float4(a[4]*inv, a[5]*inv, a[6]*inv, a[7]*inv);
        }
        __syncthreads();
        // ---- phase B: accumulate fv1/fv2 (and a_sum on spare threads) ----
        if (fvthr) {
            const int m0 = g * 15;
#pragma unroll
            for (int i = 0; i < 15; i++) {
                int m = m0 + i;
                const float4* av = (const float4*)&s_act[m * 8];  // broadcast
                float4 a0 = av[0], a1 = av[1];
                float xv = s_xT[f * MP + m];
                float aa[8] = {a0.x, a0.y, a0.z, a0.w, a1.x, a1.y, a1.z, a1.w};
#pragma unroll
                for (int c = 0; c < 8; c++) {
                    float t = aa[c] * xv;
                    acc1[c] += t;
                    acc2[c] += t * xv;
                }
            }
        } else {
            const int m0 = acc_p * 30;
#pragma unroll 6
            for (int i = 0; i < 30; i++)
                asum_p += s_act[(m0 + i) * 8 + acc_c];
        }
    }
    __syncthreads();

    // ---- reduce the 8 m-groups; s_xT reused as scratch ----
    float* s_red = s_xT;
    if (fvthr) {
        float4* rv = (float4*)&s_red[(g * Fdim + f) * 8];
        rv[0] = make_float4(acc1[0], acc1[1], acc1[2], acc1[3]);
        rv[1] = make_float4(acc1[4], acc1[5], acc1[6], acc1[7]);
    } else {
        s_asum[acc_p * 8 + acc_c] = asum_p;
    }
    __syncthreads();
    const int f2 = tid >> 3;
    const int c2 = tid & 7;
    float fv1raw = 0.f, fv2raw = 0.f;
    if (fvthr) {
#pragma unroll
        for (int gg = 0; gg < 8; gg++)
            fv1raw += s_red[(gg * Fdim + f2) * 8 + c2];
    }
    __syncthreads();
    if (fvthr) {
        float4* rv = (float4*)&s_red[(g * Fdim + f) * 8];
        rv[0] = make_float4(acc2[0], acc2[1], acc2[2], acc2[3]);
        rv[1] = make_float4(acc2[4], acc2[5], acc2[6], acc2[7]);
    }
    if (tid < 8) {
        float s = s_asum[tid] + s_asum[8 + tid] + s_asum[16 + tid] + s_asum[24 + tid];
        s_asum[tid] = s;  // row 0 = final a_sum[c]
    }
    __syncthreads();

    float fv1 = 0.f, fv2 = 0.f;
    if (fvthr) {
#pragma unroll
        for (int gg = 0; gg < 8; gg++)
            fv2raw += s_red[(gg * Fdim + f2) * 8 + c2];
        float A   = s_asum[c2];
        float w2v = gw2[tid];           // tid == f2*8 + c2, coalesced
        float cv  = gcov[tid];
        float cw  = cv * cv + 1e-6f;
        fv1 = (fv1raw - A * w2v) / cw;
        fv2 = (A * w2v * w2v + fv2raw - 2.f * fv1raw * w2v) / (cw * cw) - A;
        atomicAdd(&s_q1[c2], fv1 * fv1);
        atomicAdd(&s_q2, fv2 * fv2);
    }
    __syncthreads();
    if (tid == 0) {
        float G = 0.f;
#pragma unroll
        for (int c = 0; c < 8; c++) {
            float q = s_q1[c];
            float r = rsqrtf(fmaxf(q, 1e-12f));
            s_rc[c] = r;
            G += q * r * r;
        }
        s_rg = rsqrtf(fmaxf(G, 1e-12f));
        float q2  = s_q2;
        float r2  = rsqrtf(fmaxf(q2, 1e-12f));
        float q2b = q2 * r2 * r2;                       // second (idempotent) normalize
        s_sc2 = r2 * rsqrtf(fmaxf(q2b, 1e-12f));
    }
    __syncthreads();
    float* s_fv = s_xT + 3840;       // 960 floats
    if (fvthr) {
        s_fv[tid]       = fv1 * s_rc[c2] * s_rg;   // flat index = f*C + c = tid
        s_fv[480 + tid] = fv2 * s_sc2;
    }
    __syncthreads();
    // ---- final matvec: out[b, :] = fv @ H  (960 x 18) ----
    float* s_part = s_xT + 3840 + 960;  // 486 floats
    if (tid < 486) {
        int o  = tid % 18;
        int gg = tid / 18;
        float acc = 0.f;
        for (int j = gg; j < 960; j += 27)
            acc += s_fv[j] * gH[j * 18 + o];
        s_part[tid] = acc;
    }
    __syncthreads();
    if (tid < 18) {
        float s = 0.f;
#pragma unroll
        for (int gg = 0; gg < 27; gg++) s += s_part[gg * 18 + tid];
        gout[b * OUTd + tid] = s;
    }
}

extern "C" void kernel_launch(void* const* d_in, const int* in_sizes, int n_in,
                              void* d_out, int out_size) {
    const float* x    = (const float*)d_in[0];
    const float* W    = (const float*)d_in[1];
    const float* cov  = (const float*)d_in[2];
    const float* bias = (const float*)d_in[3];
    const float* w2   = (const float*)d_in[4];
    const float* H    = (const float*)d_in[5];
    float* out = (float*)d_out;

    int B = in_sizes[0] / (Mdim * Fdim);   // 2048
    netfv_kernel<<<B, NTHR>>>(x, W, cov, bias, w2, H, out);
}

// round 2
// speedup vs baseline: 1.1952x; 1.1952x over previous
#include <cuda_runtime.h>

#define Fdim 60
#define Mdim 600
#define Cdim 8
#define OUTd 18
#define MT   120
#define NCH  5
#define MP   121
#define NTHR 480
#define XTSZ (Fdim*MP)   // 7260 floats per x buffer

typedef unsigned long long u64;

__device__ __forceinline__ u64 pk2(float x, float y) {
    u64 r; asm("mov.b64 %0,{%1,%2};" : "=l"(r) : "f"(x), "f"(y)); return r;
}
__device__ __forceinline__ float2 upk2(u64 v) {
    float2 r; asm("mov.b64 {%0,%1},%2;" : "=f"(r.x), "=f"(r.y) : "l"(v)); return r;
}
__device__ __forceinline__ u64 ffma2(u64 a, u64 b, u64 c) {
    u64 d; asm("fma.rn.f32x2 %0,%1,%2,%3;" : "=l"(d) : "l"(a), "l"(b), "l"(c)); return d;
}
__device__ __forceinline__ u64 fadd2(u64 a, u64 b) {
    u64 d; asm("add.rn.f32x2 %0,%1,%2;" : "=l"(d) : "l"(a), "l"(b)); return d;
}

__global__ __launch_bounds__(NTHR, 2)
void netfv_kernel(const float* __restrict__ gx,     // [B*600, 60]
                  const float* __restrict__ gW,     // [60, 8]
                  const float* __restrict__ gcov,   // [60, 8]
                  const float* __restrict__ gbias,  // [8]
                  const float* __restrict__ gw2,    // [60, 8]
                  const float* __restrict__ gH,     // [960, 18]
                  float* __restrict__ gout)         // [B, 18]
{
    extern __shared__ float sm[];
    float* s_x0   = sm;                       // XTSZ
    float* s_x1   = sm + XTSZ;                // XTSZ
    float* s_a0   = sm + 2*XTSZ;              // 960
    float* s_a1   = s_a0 + MT*Cdim;           // 960
    float* s_W    = s_a1 + MT*Cdim;           // 480 (offset 16440 fl, 16B aligned)
    float* s_bias = s_W + 480;                // 8
    float* s_ap   = s_bias + 8;               // 120  (per-warp a_sum partials)
    float* s_q1p  = s_ap + 120;               // 120
    float* s_q2p  = s_q1p + 120;              // 15
    float* s_msc  = s_q2p + 15;               // 18: [0..7]=asum, [8..15]=rc, [16]=rg, [17]=sc2

    const int tid  = threadIdx.x;
    const int b    = blockIdx.x;
    const int g    = tid / Fdim;              // 0..7  (phase-B m-group)
    const int f    = tid - g * Fdim;          // 0..59 (phase-B feature)
    const int w    = tid >> 5;                // warp 0..14
    const int lane = tid & 31;

    s_W[tid < 480 ? tid : 0] = gW[tid < 480 ? tid : 0];
    if (tid < Cdim) s_bias[tid] = gbias[tid];
    if (tid < 120)  s_ap[tid] = 0.f;

    const float* xb = gx + (size_t)b * (Mdim * Fdim);

    // ---- prologue: copy chunk 0 (k = f is loop-invariant; m = g + 8i) ----
    {
        const float* src = xb;
        float* dst = s_x0 + f * MP + g;
#pragma unroll
        for (int i = 0; i < 15; i++) dst[8 * i] = src[tid + i * NTHR];
    }
    __syncthreads();

    const int am   = tid >> 2;                // phase-A row 0..119
    const int aj   = tid & 3;                 // phase-A k-quarter
    const int aj15 = aj * 15;

    u64 c1[4], c2a[4];
#pragma unroll
    for (int p = 0; p < 4; p++) { c1[p] = 0ULL; c2a[p] = 0ULL; }

    for (int ch = 0; ch < NCH; ++ch) {
        float* s_xc = (ch & 1) ? s_x1 : s_x0;
        float* s_xn = (ch & 1) ? s_x0 : s_x1;
        float* s_ac = (ch & 1) ? s_a1 : s_a0;

        // stage next chunk's global loads (latency hidden behind phase A)
        float st[15];
        if (ch < NCH - 1) {
            const float* src = xb + (ch + 1) * (MT * Fdim);
#pragma unroll
            for (int i = 0; i < 15; i++) st[i] = src[tid + i * NTHR];
        }

        // ---- phase A: act = softmax(x @ W + bias), 480 threads ----
        {
            u64 aa0 = 0, aa1 = 0, aa2 = 0, aa3 = 0;
            const float* xp = s_xc + am;
#pragma unroll
            for (int k = 0; k < 15; k++) {
                int kk = aj15 + k;
                float xk = xp[kk * MP];
                u64 xx = pk2(xk, xk);
                const ulonglong2* wp = (const ulonglong2*)&s_W[kk * 8];
                ulonglong2 wA = wp[0], wB = wp[1];
                aa0 = ffma2(xx, wA.x, aa0);
                aa1 = ffma2(xx, wA.y, aa1);
                aa2 = ffma2(xx, wB.x, aa2);
                aa3 = ffma2(xx, wB.y, aa3);
            }
            // reduce k-quarters across the 4 j-lanes
            aa0 = fadd2(aa0, __shfl_xor_sync(0xffffffffu, aa0, 1));
            aa1 = fadd2(aa1, __shfl_xor_sync(0xffffffffu, aa1, 1));
            aa2 = fadd2(aa2, __shfl_xor_sync(0xffffffffu, aa2, 1));
            aa3 = fadd2(aa3, __shfl_xor_sync(0xffffffffu, aa3, 1));
            aa0 = fadd2(aa0, __shfl_xor_sync(0xffffffffu, aa0, 2));
            aa1 = fadd2(aa1, __shfl_xor_sync(0xffffffffu, aa1, 2));
            aa2 = fadd2(aa2, __shfl_xor_sync(0xffffffffu, aa2, 2));
            aa3 = fadd2(aa3, __shfl_xor_sync(0xffffffffu, aa3, 2));
            float2 p0 = upk2(aa0), p1 = upk2(aa1), p2 = upk2(aa2), p3 = upk2(aa3);
            float b0 = s_bias[0], b1 = s_bias[1], b2 = s_bias[2], b3 = s_bias[3];
            float b4 = s_bias[4], b5 = s_bias[5], b6 = s_bias[6], b7 = s_bias[7];
            p0.x += b0; p0.y += b1; p1.x += b2; p1.y += b3;
            p2.x += b4; p2.y += b5; p3.x += b6; p3.y += b7;
            float mx = fmaxf(fmaxf(fmaxf(p0.x, p0.y), fmaxf(p1.x, p1.y)),
                             fmaxf(fmaxf(p2.x, p2.y), fmaxf(p3.x, p3.y)));
            // this lane's cluster pair (c = 2*aj, 2*aj+1)
            float2 mp = (aj < 2) ? ((aj == 0) ? p0 : p1) : ((aj == 2) ? p2 : p3);
            float e0 = __expf(mp.x - mx);
            float e1 = __expf(mp.y - mx);
            float s2 = e0 + e1;
            s2 += __shfl_xor_sync(0xffffffffu, s2, 1);
            s2 += __shfl_xor_sync(0xffffffffu, s2, 2);
            float inv = __fdividef(1.f, s2);
            float v0 = e0 * inv, v1 = e1 * inv;
            *(float2*)&s_ac[am * 8 + 2 * aj] = make_float2(v0, v1);
            // per-warp a_sum partials (reduce over the 8 rows in this warp)
            float r0 = v0, r1 = v1;
            r0 += __shfl_xor_sync(0xffffffffu, r0, 4);
            r1 += __shfl_xor_sync(0xffffffffu, r1, 4);
            r0 += __shfl_xor_sync(0xffffffffu, r0, 8);
            r1 += __shfl_xor_sync(0xffffffffu, r1, 8);
            r0 += __shfl_xor_sync(0xffffffffu, r0, 16);
            r1 += __shfl_xor_sync(0xffffffffu, r1, 16);
            if (lane < 4) {
                s_ap[w * 8 + 2 * aj]     += r0;
                s_ap[w * 8 + 2 * aj + 1] += r1;
            }
        }
        // commit staged next chunk into the other buffer
        if (ch < NCH - 1) {
            float* dst = s_xn + f * MP + g;
#pragma unroll
            for (int i = 0; i < 15; i++) dst[8 * i] = st[i];
        }
        __syncthreads();

        // ---- phase B: fv1/fv2 accumulation, packed f32x2 ----
        {
            const float* xrow = s_xc + f * MP;
            const ulonglong2* arow = (const ulonglong2*)s_ac;
            const int m0 = g * 15;
#pragma unroll
            for (int i = 0; i < 15; i++) {
                int m = m0 + i;
                float xv = xrow[m];
                ulonglong2 A0 = arow[m * 2];
                ulonglong2 A1 = arow[m * 2 + 1];
                u64 xx = pk2(xv, xv);
                float xsq = xv * xv;
                u64 xq = pk2(xsq, xsq);
                c1[0]  = ffma2(A0.x, xx, c1[0]);
                c2a[0] = ffma2(A0.x, xq, c2a[0]);
                c1[1]  = ffma2(A0.y, xx, c1[1]);
                c2a[1] = ffma2(A0.y, xq, c2a[1]);
                c1[2]  = ffma2(A1.x, xx, c1[2]);
                c2a[2] = ffma2(A1.x, xq, c2a[2]);
                c1[3]  = ffma2(A1.y, xx, c1[3]);
                c2a[3] = ffma2(A1.y, xq, c2a[3]);
            }
        }
        __syncthreads();
    }

    // ================= epilogue =================
    float* s_red = s_x0;            // 3840 floats
    float* s_fv  = s_x0 + 3840;     // 960
    float* s_pt  = s_x0 + 4800;     // 468

    {   // dump acc1 per (g,f)
        float2 q0 = upk2(c1[0]), q1 = upk2(c1[1]), q2v = upk2(c1[2]), q3 = upk2(c1[3]);
        float4* rp = (float4*)&s_red[tid * 8];
        rp[0] = make_float4(q0.x, q0.y, q1.x, q1.y);
        rp[1] = make_float4(q2v.x, q2v.y, q3.x, q3.y);
    }
    if (tid < 8) {
        float A = 0.f;
#pragma unroll
        for (int ww = 0; ww < 15; ww++) A += s_ap[ww * 8 + tid];
        s_msc[tid] = A;             // final a_sum[c]
    }
    __syncthreads();
    float fv1raw = 0.f;
#pragma unroll
    for (int gg = 0; gg < 8; gg++) fv1raw += s_red[gg * 480 + tid];
    __syncthreads();
    {   // dump acc2
        float2 q0 = upk2(c2a[0]), q1 = upk2(c2a[1]), q2v = upk2(c2a[2]), q3 = upk2(c2a[3]);
        float4* rp = (float4*)&s_red[tid * 8];
        rp[0] = make_float4(q0.x, q0.y, q1.x, q1.y);
        rp[1] = make_float4(q2v.x, q2v.y, q3.x, q3.y);
    }
    __syncthreads();
    float fv2raw = 0.f;
#pragma unroll
    for (int gg = 0; gg < 8; gg++) fv2raw += s_red[gg * 480 + tid];

    // thread now owns (f2 = tid>>3, c2 = tid&7); flat index f2*8+c2 == tid
    const int c2i = tid & 7;
    float Asum = s_msc[c2i];
    float w2v  = gw2[tid];
    float cv   = gcov[tid];
    float cw   = cv * cv + 1e-6f;
    float fv1  = (fv1raw - Asum * w2v) / cw;
    float fv2  = (Asum * w2v * w2v + fv2raw - 2.f * fv1raw * w2v) / (cw * cw) - Asum;

    // norms: q1 per cluster (lanes sharing lane&7), q2 global
    float sq1 = fv1 * fv1;
    float sq2 = fv2 * fv2;
    sq1 += __shfl_xor_sync(0xffffffffu, sq1, 8);
    sq1 += __shfl_xor_sync(0xffffffffu, sq1, 16);
    sq2 += __shfl_xor_sync(0xffffffffu, sq2, 1);
    sq2 += __shfl_xor_sync(0xffffffffu, sq2, 2);
    sq2 += __shfl_xor_sync(0xffffffffu, sq2, 4);
    sq2 += __shfl_xor_sync(0xffffffffu, sq2, 8);
    sq2 += __shfl_xor_sync(0xffffffffu, sq2, 16);
    if (lane < 8)   s_q1p[w * 8 + lane] = sq1;
    if (lane == 0)  s_q2p[w] = sq2;
    __syncthreads();
    if (tid == 0) {
        float G = 0.f;
#pragma unroll
        for (int c = 0; c < 8; c++) {
            float q = 0.f;
#pragma unroll
            for (int ww = 0; ww < 15; ww++) q += s_q1p[ww * 8 + c];
            float r = rsqrtf(fmaxf(q, 1e-12f));
            s_msc[8 + c] = r;
            G += q * r * r;
        }
        s_msc[16] = rsqrtf(fmaxf(G, 1e-12f));
        float q2s = 0.f;
#pragma unroll
        for (int ww = 0; ww < 15; ww++) q2s += s_q2p[ww];
        float r2  = rsqrtf(fmaxf(q2s, 1e-12f));
        float q2b = q2s * r2 * r2;
        s_msc[17] = r2 * rsqrtf(fmaxf(q2b, 1e-12f));
    }
    __syncthreads();
    s_fv[tid]       = fv1 * s_msc[8 + c2i] * s_msc[16];
    s_fv[480 + tid] = fv2 * s_msc[17];
    __syncthreads();

    // final matvec: out[b,:] = fv(960) @ H(960x18)
    if (tid < 468) {
        int ggq = tid / 18;
        int o   = tid - ggq * 18;
        float acc = 0.f;
        for (int jj = ggq; jj < 960; jj += 26)
            acc += s_fv[jj] * gH[jj * 18 + o];
        s_pt[tid] = acc;
    }
    __syncthreads();
    if (tid < 18) {
        float s = 0.f;
#pragma unroll
        for (int ggq = 0; ggq < 26; ggq++) s += s_pt[ggq * 18 + tid];
        gout[b * OUTd + tid] = s;
    }
}

extern "C" void kernel_launch(void* const* d_in, const int* in_sizes, int n_in,
                              void* d_out, int out_size) {
    const float* x    = (const float*)d_in[0];
    const float* W    = (const float*)d_in[1];
    const float* cov  = (const float*)d_in[2];
    const float* bias = (const float*)d_in[3];
    const float* w2   = (const float*)d_in[4];
    const float* H    = (const float*)d_in[5];
    float* out = (float*)d_out;

    const int smem_bytes = (2 * XTSZ + 2 * MT * Cdim + 480 + 8 + 120 + 120 + 15 + 18) * 4;
    cudaFuncSetAttribute(netfv_kernel, cudaFuncAttributeMaxDynamicSharedMemorySize, smem_bytes);

    int B = in_sizes[0] / (Mdim * Fdim);   // 2048
    netfv_kernel<<<B, NTHR, smem_bytes>>>(x, W, cov, bias, w2, H, out);
}

// round 3
// speedup vs baseline: 1.1989x; 1.0031x over previous
#include <cuda_runtime.h>

#define Fdim 60
#define Mdim 600
#define Cdim 8
#define OUTd 18
#define MT   120
#define NCH  5
#define MP   121
#define NTHR 480
#define XTSZ (Fdim*MP)   // 7260 floats per x buffer

typedef unsigned long long u64;

__device__ __forceinline__ u64 pk2(float x, float y) {
    u64 r; asm("mov.b64 %0,{%1,%2};" : "=l"(r) : "f"(x), "f"(y)); return r;
}
__device__ __forceinline__ float2 upk2(u64 v) {
    float2 r; asm("mov.b64 {%0,%1},%2;" : "=f"(r.x), "=f"(r.y) : "l"(v)); return r;
}
__device__ __forceinline__ u64 ffma2(u64 a, u64 b, u64 c) {
    u64 d; asm("fma.rn.f32x2 %0,%1,%2,%3;" : "=l"(d) : "l"(a), "l"(b), "l"(c)); return d;
}
__device__ __forceinline__ u64 fadd2(u64 a, u64 b) {
    u64 d; asm("add.rn.f32x2 %0,%1,%2;" : "=l"(d) : "l"(a), "l"(b)); return d;
}

__global__ __launch_bounds__(NTHR, 2)
void netfv_kernel(const float* __restrict__ gx,     // [B*600, 60]
                  const float* __restrict__ gW,     // [60, 8]
                  const float* __restrict__ gcov,   // [60, 8]
                  const float* __restrict__ gbias,  // [8]
                  const float* __restrict__ gw2,    // [60, 8]
                  const float* __restrict__ gH,     // [960, 18]
                  float* __restrict__ gout)         // [B, 18]
{
    extern __shared__ float sm[];
    float* s_x0   = sm;                       // XTSZ
    float* s_x1   = sm + XTSZ;                // XTSZ
    float* s_a0   = sm + 2*XTSZ;              // 960
    float* s_a1   = s_a0 + MT*Cdim;           // 960
    float* s_W    = s_a1 + MT*Cdim;           // 480 (offset 16440 fl, 16B aligned)
    float* s_bias = s_W + 480;                // 8
    float* s_ap   = s_bias + 8;               // 120  (per-warp a_sum partials)
    float* s_q1p  = s_ap + 120;               // 120
    float* s_q2p  = s_q1p + 120;              // 15
    float* s_msc  = s_q2p + 15;               // 18: [0..7]=asum, [8..15]=rc, [16]=rg, [17]=sc2

    const int tid  = threadIdx.x;
    const int b    = blockIdx.x;
    const int g    = tid / Fdim;              // 0..7  (phase-B m-group)
    const int f    = tid - g * Fdim;          // 0..59 (phase-B feature)
    const int w    = tid >> 5;                // warp 0..14
    const int lane = tid & 31;

    s_W[tid < 480 ? tid : 0] = gW[tid < 480 ? tid : 0];
    if (tid < Cdim) s_bias[tid] = gbias[tid];
    if (tid < 120)  s_ap[tid] = 0.f;

    const float* xb = gx + (size_t)b * (Mdim * Fdim);

    // ---- prologue: copy chunk 0 (k = f is loop-invariant; m = g + 8i) ----
    {
        const float* src = xb;
        float* dst = s_x0 + f * MP + g;
#pragma unroll
        for (int i = 0; i < 15; i++) dst[8 * i] = src[tid + i * NTHR];
    }
    __syncthreads();

    const int am   = tid >> 2;                // phase-A row 0..119
    const int aj   = tid & 3;                 // phase-A k-quarter
    const int aj15 = aj * 15;

    u64 c1[4], c2a[4];
#pragma unroll
    for (int p = 0; p < 4; p++) { c1[p] = 0ULL; c2a[p] = 0ULL; }

    for (int ch = 0; ch < NCH; ++ch) {
        float* s_xc = (ch & 1) ? s_x1 : s_x0;
        float* s_xn = (ch & 1) ? s_x0 : s_x1;
        float* s_ac = (ch & 1) ? s_a1 : s_a0;

        // stage next chunk's global loads (latency hidden behind phase A)
        float st[15];
        if (ch < NCH - 1) {
            const float* src = xb + (ch + 1) * (MT * Fdim);
#pragma unroll
            for (int i = 0; i < 15; i++) st[i] = src[tid + i * NTHR];
        }

        // ---- phase A: act = softmax(x @ W + bias), 480 threads ----
        {
            u64 aa0 = 0, aa1 = 0, aa2 = 0, aa3 = 0;
            const float* xp = s_xc + am;
#pragma unroll
            for (int k = 0; k < 15; k++) {
                int kk = aj15 + k;
                float xk = xp[kk * MP];
                u64 xx = pk2(xk, xk);
                const ulonglong2* wp = (const ulonglong2*)&s_W[kk * 8];
                ulonglong2 wA = wp[0], wB = wp[1];
                aa0 = ffma2(xx, wA.x, aa0);
                aa1 = ffma2(xx, wA.y, aa1);
                aa2 = ffma2(xx, wB.x, aa2);
                aa3 = ffma2(xx, wB.y, aa3);
            }
            // reduce k-quarters across the 4 j-lanes
            aa0 = fadd2(aa0, __shfl_xor_sync(0xffffffffu, aa0, 1));
            aa1 = fadd2(aa1, __shfl_xor_sync(0xffffffffu, aa1, 1));
            aa2 = fadd2(aa2, __shfl_xor_sync(0xffffffffu, aa2, 1));
            aa3 = fadd2(aa3, __shfl_xor_sync(0xffffffffu, aa3, 1));
            aa0 = fadd2(aa0, __shfl_xor_sync(0xffffffffu, aa0, 2));
            aa1 = fadd2(aa1, __shfl_xor_sync(0xffffffffu, aa1, 2));
            aa2 = fadd2(aa2, __shfl_xor_sync(0xffffffffu, aa2, 2));
            aa3 = fadd2(aa3, __shfl_xor_sync(0xffffffffu, aa3, 2));
            float2 p0 = upk2(aa0), p1 = upk2(aa1), p2 = upk2(aa2), p3 = upk2(aa3);
            float b0 = s_bias[0], b1 = s_bias[1], b2 = s_bias[2], b3 = s_bias[3];
            float b4 = s_bias[4], b5 = s_bias[5], b6 = s_bias[6], b7 = s_bias[7];
            p0.x += b0; p0.y += b1; p1.x += b2; p1.y += b3;
            p2.x += b4; p2.y += b5; p3.x += b6; p3.y += b7;
            float mx = fmaxf(fmaxf(fmaxf(p0.x, p0.y), fmaxf(p1.x, p1.y)),
                             fmaxf(fmaxf(p2.x, p2.y), fmaxf(p3.x, p3.y)));
            // this lane's cluster pair (c = 2*aj, 2*aj+1)
            float2 mp = (aj < 2) ? ((aj == 0) ? p0 : p1) : ((aj == 2) ? p2 : p3);
            float e0 = __expf(mp.x - mx);
            float e1 = __expf(mp.y - mx);
            float s2 = e0 + e1;
            s2 += __shfl_xor_sync(0xffffffffu, s2, 1);
            s2 += __shfl_xor_sync(0xffffffffu, s2, 2);
            float inv = __fdividef(1.f, s2);
            float v0 = e0 * inv, v1 = e1 * inv;
            *(float2*)&s_ac[am * 8 + 2 * aj] = make_float2(v0, v1);
            // per-warp a_sum partials (reduce over the 8 rows in this warp)
            float r0 = v0, r1 = v1;
            r0 += __shfl_xor_sync(0xffffffffu, r0, 4);
            r1 += __shfl_xor_sync(0xffffffffu, r1, 4);
            r0 += __shfl_xor_sync(0xffffffffu, r0, 8);
            r1 += __shfl_xor_sync(0xffffffffu, r1, 8);
            r0 += __shfl_xor_sync(0xffffffffu, r0, 16);
            r1 += __shfl_xor_sync(0xffffffffu, r1, 16);
            if (lane < 4) {
                s_ap[w * 8 + 2 * aj]     += r0;
                s_ap[w * 8 + 2 * aj + 1] += r1;
            }
        }
        // commit staged next chunk into the other buffer
        if (ch < NCH - 1) {
            float* dst = s_xn + f * MP + g;
#pragma unroll
            for (int i = 0; i < 15; i++) dst[8 * i] = st[i];
        }
        __syncthreads();

        // ---- phase B: fv1/fv2 accumulation, packed f32x2 ----
        {
            const float* xrow = s_xc + f * MP;
            const ulonglong2* arow = (const ulonglong2*)s_ac;
            const int m0 = g * 15;
#pragma unroll
            for (int i = 0; i < 15; i++) {
                int m = m0 + i;
                float xv = xrow[m];
                ulonglong2 A0 = arow[m * 2];
                ulonglong2 A1 = arow[m * 2 + 1];
                u64 xx = pk2(xv, xv);
                float xsq = xv * xv;
                u64 xq = pk2(xsq, xsq);
                c1[0]  = ffma2(A0.x, xx, c1[0]);
                c2a[0] = ffma2(A0.x, xq, c2a[0]);
                c1[1]  = ffma2(A0.y, xx, c1[1]);
                c2a[1] = ffma2(A0.y, xq, c2a[1]);
                c1[2]  = ffma2(A1.x, xx, c1[2]);
                c2a[2] = ffma2(A1.x, xq, c2a[2]);
                c1[3]  = ffma2(A1.y, xx, c1[3]);
                c2a[3] = ffma2(A1.y, xq, c2a[3]);
            }
        }
        __syncthreads();
    }

    // ================= epilogue =================
    float* s_red = s_x0;            // 3840 floats
    float* s_fv  = s_x0 + 3840;     // 960
    float* s_pt  = s_x0 + 4800;     // 468

    {   // dump acc1 per (g,f)
        float2 q0 = upk2(c1[0]), q1 = upk2(c1[1]), q2v = upk2(c1[2]), q3 = upk2(c1[3]);
        float4* rp = (float4*)&s_red[tid * 8];
        rp[0] = make_float4(q0.x, q0.y, q1.x, q1.y);
        rp[1] = make_float4(q2v.x, q2v.y, q3.x, q3.y);
    }
    if (tid < 8) {
        float A = 0.f;
#pragma unroll
        for (int ww = 0; ww < 15; ww++) A += s_ap[ww * 8 + tid];
        s_msc[tid] = A;             // final a_sum[c]
    }
    __syncthreads();
    float fv1raw = 0.f;
#pragma unroll
    for (int gg = 0; gg < 8; gg++) fv1raw += s_red[gg * 480 + tid];
    __syncthreads();
    {   // dump acc2
        float2 q0 = upk2(c2a[0]), q1 = upk2(c2a[1]), q2v = upk2(c2a[2]), q3 = upk2(c2a[3]);
        float4* rp = (float4*)&s_red[tid * 8];
        rp[0] = make_float4(q0.x, q0.y, q1.x, q1.y);
        rp[1] = make_float4(q2v.x, q2v.y, q3.x, q3.y);
    }
    __syncthreads();
    float fv2raw = 0.f;
#pragma unroll
    for (int gg = 0; gg < 8; gg++) fv2raw += s_red[gg * 480 + tid];

    // thread now owns (f2 = tid>>3, c2 = tid&7); flat index f2*8+c2 == tid
    const int c2i = tid & 7;
    float Asum = s_msc[c2i];
    float w2v  = gw2[tid];
    float cv   = gcov[tid];
    float cw   = cv * cv + 1e-6f;
    float fv1  = (fv1raw - Asum * w2v) / cw;
    float fv2  = (Asum * w2v * w2v + fv2raw - 2.f * fv1raw * w2v) / (cw * cw) - Asum;

    // norms: q1 per cluster (lanes sharing lane&7), q2 global
    float sq1 = fv1 * fv1;
    float sq2 = fv2 * fv2;
    sq1 += __shfl_xor_sync(0xffffffffu, sq1, 8);
    sq1 += __shfl_xor_sync(0xffffffffu, sq1, 16);
    sq2 += __shfl_xor_sync(0xffffffffu, sq2, 1);
    sq2 += __shfl_xor_sync(0xffffffffu, sq2, 2);
    sq2 += __shfl_xor_sync(0xffffffffu, sq2, 4);
    sq2 += __shfl_xor_sync(0xffffffffu, sq2, 8);
    sq2 += __shfl_xor_sync(0xffffffffu, sq2, 16);
    if (lane < 8)   s_q1p[w * 8 + lane] = sq1;
    if (lane == 0)  s_q2p[w] = sq2;
    __syncthreads();
    if (tid == 0) {
        float G = 0.f;
#pragma unroll
        for (int c = 0; c < 8; c++) {
            float q = 0.f;
#pragma unroll
            for (int ww = 0; ww < 15; ww++) q += s_q1p[ww * 8 + c];
            float r = rsqrtf(fmaxf(q, 1e-12f));
            s_msc[8 + c] = r;
            G += q * r * r;
        }
        s_msc[16] = rsqrtf(fmaxf(G, 1e-12f));
        float q2s = 0.f;
#pragma unroll
        for (int ww = 0; ww < 15; ww++) q2s += s_q2p[ww];
        float r2  = rsqrtf(fmaxf(q2s, 1e-12f));
        float q2b = q2s * r2 * r2;
        s_msc[17] = r2 * rsqrtf(fmaxf(q2b, 1e-12f));
    }
    __syncthreads();
    s_fv[tid]       = fv1 * s_msc[8 + c2i] * s_msc[16];
    s_fv[480 + tid] = fv2 * s_msc[17];
    __syncthreads();

    // final matvec: out[b,:] = fv(960) @ H(960x18)
    if (tid < 468) {
        int ggq = tid / 18;
        int o   = tid - ggq * 18;
        float acc = 0.f;
        for (int jj = ggq; jj < 960; jj += 26)
            acc += s_fv[jj] * gH[jj * 18 + o];
        s_pt[tid] = acc;
    }
    __syncthreads();
    if (tid < 18) {
        float s = 0.f;
#pragma unroll
        for (int ggq = 0; ggq < 26; ggq++) s += s_pt[ggq * 18 + tid];
        gout[b * OUTd + tid] = s;
    }
}

extern "C" void kernel_launch(void* const* d_in, const int* in_sizes, int n_in,
                              void* d_out, int out_size) {
    const float* x    = (const float*)d_in[0];
    const float* W    = (const float*)d_in[1];
    const float* cov  = (const float*)d_in[2];
    const float* bias = (const float*)d_in[3];
    const float* w2   = (const float*)d_in[4];
    const float* H    = (const float*)d_in[5];
    float* out = (float*)d_out;

    const int smem_bytes = (2 * XTSZ + 2 * MT * Cdim + 480 + 8 + 120 + 120 + 15 + 18) * 4;
    cudaFuncSetAttribute(netfv_kernel, cudaFuncAttributeMaxDynamicSharedMemorySize, smem_bytes);

    int B = in_sizes[0] / (Mdim * Fdim);   // 2048
    netfv_kernel<<<B, NTHR, smem_bytes>>>(x, W, cov, bias, w2, H, out);
}

// round 4
// speedup vs baseline: 1.2007x; 1.0016x over previous
#include <cuda_runtime.h>

#define Fdim 60
#define Mdim 600
#define Cdim 8
#define OUTd 18
#define MT   120
#define NCH  5
#define MP   121
#define NTHR 480
#define XTSZ (Fdim*MP)   // 7260 floats per x buffer

typedef unsigned long long u64;

__device__ __forceinline__ u64 pk2(float x, float y) {
    u64 r; asm("mov.b64 %0,{%1,%2};" : "=l"(r) : "f"(x), "f"(y)); return r;
}
__device__ __forceinline__ float2 upk2(u64 v) {
    float2 r; asm("mov.b64 {%0,%1},%2;" : "=f"(r.x), "=f"(r.y) : "l"(v)); return r;
}
__device__ __forceinline__ u64 ffma2(u64 a, u64 b, u64 c) {
    u64 d; asm("fma.rn.f32x2 %0,%1,%2,%3;" : "=l"(d) : "l"(a), "l"(b), "l"(c)); return d;
}
__device__ __forceinline__ u64 fadd2(u64 a, u64 b) {
    u64 d; asm("add.rn.f32x2 %0,%1,%2;" : "=l"(d) : "l"(a), "l"(b)); return d;
}

__global__ __launch_bounds__(NTHR, 2)
void netfv_kernel(const float* __restrict__ gx,     // [B*600, 60]
                  const float* __restrict__ gW,     // [60, 8]
                  const float* __restrict__ gcov,   // [60, 8]
                  const float* __restrict__ gbias,  // [8]
                  const float* __restrict__ gw2,    // [60, 8]
                  const float* __restrict__ gH,     // [960, 18]
                  float* __restrict__ gout)         // [B, 18]
{
    extern __shared__ float sm[];
    float* s_x0   = sm;                       // XTSZ
    float* s_x1   = sm + XTSZ;                // XTSZ
    float* s_a0   = sm + 2*XTSZ;              // 960
    float* s_a1   = s_a0 + MT*Cdim;           // 960
    float* s_W    = s_a1 + MT*Cdim;           // 480 (offset 16440 fl, 16B aligned)
    float* s_bias = s_W + 480;                // 8
    float* s_ap   = s_bias + 8;               // 120  (per-warp a_sum partials)
    float* s_q1p  = s_ap + 120;               // 120
    float* s_q2p  = s_q1p + 120;              // 15
    float* s_msc  = s_q2p + 15;               // 18: [0..7]=asum, [8..15]=rc, [16]=rg, [17]=sc2

    const int tid  = threadIdx.x;
    const int b    = blockIdx.x;
    const int g    = tid / Fdim;              // 0..7  (phase-B m-group)
    const int f    = tid - g * Fdim;          // 0..59 (phase-B feature)
    const int w    = tid >> 5;                // warp 0..14
    const int lane = tid & 31;

    s_W[tid < 480 ? tid : 0] = gW[tid < 480 ? tid : 0];
    if (tid < Cdim) s_bias[tid] = gbias[tid];
    if (tid < 120)  s_ap[tid] = 0.f;

    const float* xb = gx + (size_t)b * (Mdim * Fdim);

    // ---- prologue: copy chunk 0 (k = f is loop-invariant; m = g + 8i) ----
    {
        const float* src = xb;
        float* dst = s_x0 + f * MP + g;
#pragma unroll
        for (int i = 0; i < 15; i++) dst[8 * i] = src[tid + i * NTHR];
    }
    __syncthreads();

    const int am   = tid >> 2;                // phase-A row 0..119
    const int aj   = tid & 3;                 // phase-A k-quarter
    const int aj15 = aj * 15;

    u64 c1[4], c2a[4];
#pragma unroll
    for (int p = 0; p < 4; p++) { c1[p] = 0ULL; c2a[p] = 0ULL; }

    for (int ch = 0; ch < NCH; ++ch) {
        float* s_xc = (ch & 1) ? s_x1 : s_x0;
        float* s_xn = (ch & 1) ? s_x0 : s_x1;
        float* s_ac = (ch & 1) ? s_a1 : s_a0;

        // stage next chunk's global loads (latency hidden behind phase A)
        float st[15];
        if (ch < NCH - 1) {
            const float* src = xb + (ch + 1) * (MT * Fdim);
#pragma unroll
            for (int i = 0; i < 15; i++) st[i] = src[tid + i * NTHR];
        }

        // ---- phase A: act = softmax(x @ W + bias), 480 threads ----
        {
            u64 aa0 = 0, aa1 = 0, aa2 = 0, aa3 = 0;
            const float* xp = s_xc + am;
#pragma unroll
            for (int k = 0; k < 15; k++) {
                int kk = aj15 + k;
                float xk = xp[kk * MP];
                u64 xx = pk2(xk, xk);
                const ulonglong2* wp = (const ulonglong2*)&s_W[kk * 8];
                ulonglong2 wA = wp[0], wB = wp[1];
                aa0 = ffma2(xx, wA.x, aa0);
                aa1 = ffma2(xx, wA.y, aa1);
                aa2 = ffma2(xx, wB.x, aa2);
                aa3 = ffma2(xx, wB.y, aa3);
            }
            // reduce k-quarters across the 4 j-lanes
            aa0 = fadd2(aa0, __shfl_xor_sync(0xffffffffu, aa0, 1));
            aa1 = fadd2(aa1, __shfl_xor_sync(0xffffffffu, aa1, 1));
            aa2 = fadd2(aa2, __shfl_xor_sync(0xffffffffu, aa2, 1));
            aa3 = fadd2(aa3, __shfl_xor_sync(0xffffffffu, aa3, 1));
            aa0 = fadd2(aa0, __shfl_xor_sync(0xffffffffu, aa0, 2));
            aa1 = fadd2(aa1, __shfl_xor_sync(0xffffffffu, aa1, 2));
            aa2 = fadd2(aa2, __shfl_xor_sync(0xffffffffu, aa2, 2));
            aa3 = fadd2(aa3, __shfl_xor_sync(0xffffffffu, aa3, 2));
            float2 p0 = upk2(aa0), p1 = upk2(aa1), p2 = upk2(aa2), p3 = upk2(aa3);
            float b0 = s_bias[0], b1 = s_bias[1], b2 = s_bias[2], b3 = s_bias[3];
            float b4 = s_bias[4], b5 = s_bias[5], b6 = s_bias[6], b7 = s_bias[7];
            p0.x += b0; p0.y += b1; p1.x += b2; p1.y += b3;
            p2.x += b4; p2.y += b5; p3.x += b6; p3.y += b7;
            float mx = fmaxf(fmaxf(fmaxf(p0.x, p0.y), fmaxf(p1.x, p1.y)),
                             fmaxf(fmaxf(p2.x, p2.y), fmaxf(p3.x, p3.y)));
            // this lane's cluster pair (c = 2*aj, 2*aj+1)
            float2 mp = (aj < 2) ? ((aj == 0) ? p0 : p1) : ((aj == 2) ? p2 : p3);
            float e0 = __expf(mp.x - mx);
            float e1 = __expf(mp.y - mx);
            float s2 = e0 + e1;
            s2 += __shfl_xor_sync(0xffffffffu, s2, 1);
            s2 += __shfl_xor_sync(0xffffffffu, s2, 2);
            float inv = __fdividef(1.f, s2);
            float v0 = e0 * inv, v1 = e1 * inv;
            *(float2*)&s_ac[am * 8 + 2 * aj] = make_float2(v0, v1);
            // per-warp a_sum partials (reduce over the 8 rows in this warp)
            float r0 = v0, r1 = v1;
            r0 += __shfl_xor_sync(0xffffffffu, r0, 4);
            r1 += __shfl_xor_sync(0xffffffffu, r1, 4);
            r0 += __shfl_xor_sync(0xffffffffu, r0, 8);
            r1 += __shfl_xor_sync(0xffffffffu, r1, 8);
            r0 += __shfl_xor_sync(0xffffffffu, r0, 16);
            r1 += __shfl_xor_sync(0xffffffffu, r1, 16);
            if (lane < 4) {
                s_ap[w * 8 + 2 * aj]     += r0;
                s_ap[w * 8 + 2 * aj + 1] += r1;
            }
        }
        // commit staged next chunk into the other buffer
        if (ch < NCH - 1) {
            float* dst = s_xn + f * MP + g;
#pragma unroll
            for (int i = 0; i < 15; i++) dst[8 * i] = st[i];
        }
        __syncthreads();

        // ---- phase B: fv1/fv2 accumulation, packed f32x2 ----
        {
            const float* xrow = s_xc + f * MP;
            const ulonglong2* arow = (const ulonglong2*)s_ac;
            const int m0 = g * 15;
#pragma unroll
            for (int i = 0; i < 15; i++) {
                int m = m0 + i;
                float xv = xrow[m];
                ulonglong2 A0 = arow[m * 2];
                ulonglong2 A1 = arow[m * 2 + 1];
                u64 xx = pk2(xv, xv);
                float xsq = xv * xv;
                u64 xq = pk2(xsq, xsq);
                c1[0]  = ffma2(A0.x, xx, c1[0]);
                c2a[0] = ffma2(A0.x, xq, c2a[0]);
                c1[1]  = ffma2(A0.y, xx, c1[1]);
                c2a[1] = ffma2(A0.y, xq, c2a[1]);
                c1[2]  = ffma2(A1.x, xx, c1[2]);
                c2a[2] = ffma2(A1.x, xq, c2a[2]);
                c1[3]  = ffma2(A1.y, xx, c1[3]);
                c2a[3] = ffma2(A1.y, xq, c2a[3]);
            }
        }
        __syncthreads();
    }

    // ================= epilogue =================
    float* s_red = s_x0;            // 3840 floats
    float* s_fv  = s_x0 + 3840;     // 960
    float* s_pt  = s_x0 + 4800;     // 468

    {   // dump acc1 per (g,f)
        float2 q0 = upk2(c1[0]), q1 = upk2(c1[1]), q2v = upk2(c1[2]), q3 = upk2(c1[3]);
        float4* rp = (float4*)&s_red[tid * 8];
        rp[0] = make_float4(q0.x, q0.y, q1.x, q1.y);
        rp[1] = make_float4(q2v.x, q2v.y, q3.x, q3.y);
    }
    if (tid < 8) {
        float A = 0.f;
#pragma unroll
        for (int ww = 0; ww < 15; ww++) A += s_ap[ww * 8 + tid];
        s_msc[tid] = A;             // final a_sum[c]
    }
    __syncthreads();
    float fv1raw = 0.f;
#pragma unroll
    for (int gg = 0; gg < 8; gg++) fv1raw += s_red[gg * 480 + tid];
    __syncthreads();
    {   // dump acc2
        float2 q0 = upk2(c2a[0]), q1 = upk2(c2a[1]), q2v = upk2(c2a[2]), q3 = upk2(c2a[3]);
        float4* rp = (float4*)&s_red[tid * 8];
        rp[0] = make_float4(q0.x, q0.y, q1.x, q1.y);
        rp[1] = make_float4(q2v.x, q2v.y, q3.x, q3.y);
    }
    __syncthreads();
    float fv2raw = 0.f;
#pragma unroll
    for (int gg = 0; gg < 8; gg++) fv2raw += s_red[gg * 480 + tid];

    // thread now owns (f2 = tid>>3, c2 = tid&7); flat index f2*8+c2 == tid
    const int c2i = tid & 7;
    float Asum = s_msc[c2i];
    float w2v  = gw2[tid];
    float cv   = gcov[tid];
    float cw   = cv * cv + 1e-6f;
    float fv1  = (fv1raw - Asum * w2v) / cw;
    float fv2  = (Asum * w2v * w2v + fv2raw - 2.f * fv1raw * w2v) / (cw * cw) - Asum;

    // norms: q1 per cluster (lanes sharing lane&7), q2 global
    float sq1 = fv1 * fv1;
    float sq2 = fv2 * fv2;
    sq1 += __shfl_xor_sync(0xffffffffu, sq1, 8);
    sq1 += __shfl_xor_sync(0xffffffffu, sq1, 16);
    sq2 += __shfl_xor_sync(0xffffffffu, sq2, 1);
    sq2 += __shfl_xor_sync(0xffffffffu, sq2, 2);
    sq2 += __shfl_xor_sync(0xffffffffu, sq2, 4);
    sq2 += __shfl_xor_sync(0xffffffffu, sq2, 8);
    sq2 += __shfl_xor_sync(0xffffffffu, sq2, 16);
    if (lane < 8)   s_q1p[w * 8 + lane] = sq1;
    if (lane == 0)  s_q2p[w] = sq2;
    __syncthreads();
    if (tid == 0) {
        float G = 0.f;
#pragma unroll
        for (int c = 0; c < 8; c++) {
            float q = 0.f;
#pragma unroll
            for (int ww = 0; ww < 15; ww++) q += s_q1p[ww * 8 + c];
            float r = rsqrtf(fmaxf(q, 1e-12f));
            s_msc[8 + c] = r;
            G += q * r * r;
        }
        s_msc[16] = rsqrtf(fmaxf(G, 1e-12f));
        float q2s = 0.f;
#pragma unroll
        for (int ww = 0; ww < 15; ww++) q2s += s_q2p[ww];
        float r2  = rsqrtf(fmaxf(q2s, 1e-12f));
        float q2b = q2s * r2 * r2;
        s_msc[17] = r2 * rsqrtf(fmaxf(q2b, 1e-12f));
    }
    __syncthreads();
    s_fv[tid]       = fv1 * s_msc[8 + c2i] * s_msc[16];
    s_fv[480 + tid] = fv2 * s_msc[17];
    __syncthreads();

    // final matvec: out[b,:] = fv(960) @ H(960x18)
    if (tid < 468) {
        int ggq = tid / 18;
        int o   = tid - ggq * 18;
        float acc = 0.f;
        for (int jj = ggq; jj < 960; jj += 26)
            acc += s_fv[jj] * gH[jj * 18 + o];
        s_pt[tid] = acc;
    }
    __syncthreads();
    if (tid < 18) {
        float s = 0.f;
#pragma unroll
        for (int ggq = 0; ggq < 26; ggq++) s += s_pt[ggq * 18 + tid];
        gout[b * OUTd + tid] = s;
    }
}

extern "C" void kernel_launch(void* const* d_in, const int* in_sizes, int n_in,
                              void* d_out, int out_size) {
    const float* x    = (const float*)d_in[0];
    const float* W    = (const float*)d_in[1];
    const float* cov  = (const float*)d_in[2];
    const float* bias = (const float*)d_in[3];
    const float* w2   = (const float*)d_in[4];
    const float* H    = (const float*)d_in[5];
    float* out = (float*)d_out;

    const int smem_bytes = (2 * XTSZ + 2 * MT * Cdim + 480 + 8 + 120 + 120 + 15 + 18) * 4;
    cudaFuncSetAttribute(netfv_kernel, cudaFuncAttributeMaxDynamicSharedMemorySize, smem_bytes);

    int B = in_sizes[0] / (Mdim * Fdim);   // 2048
    netfv_kernel<<<B, NTHR, smem_bytes>>>(x, W, cov, bias, w2, H, out);
}

// round 5
// speedup vs baseline: 1.2928x; 1.0767x over previous
#include <cuda_runtime.h>

#define Fdim 60
#define Mdim 600
#define OUTd 18
#define NTHR 512
#define SR   68     // x-tile row stride; 68 % 32 == 4 -> conflict-free interleaved-k reads

typedef unsigned long long u64;

__device__ __forceinline__ u64 pk2(float x, float y) {
    u64 r; asm("mov.b64 %0,{%1,%2};" : "=l"(r) : "f"(x), "f"(y)); return r;
}
__device__ __forceinline__ float2 upk2(u64 v) {
    float2 r; asm("mov.b64 {%0,%1},%2;" : "=f"(r.x), "=f"(r.y) : "l"(v)); return r;
}
__device__ __forceinline__ u64 ffma2(u64 a, u64 b, u64 c) {
    u64 d; asm("fma.rn.f32x2 %0,%1,%2,%3;" : "=l"(d) : "l"(a), "l"(b), "l"(c)); return d;
}
__device__ __forceinline__ u64 fadd2(u64 a, u64 b) {
    u64 d; asm("add.rn.f32x2 %0,%1,%2;" : "=l"(d) : "l"(a), "l"(b)); return d;
}

__global__ __launch_bounds__(NTHR, 2)
void netfv_kernel(const float* __restrict__ gx,     // [B*600, 60]
                  const float* __restrict__ gW,     // [60, 8]
                  const float* __restrict__ gcov,   // [60, 8]
                  const float* __restrict__ gbias,  // [8]
                  const float* __restrict__ gw2,    // [60, 8]
                  const float* __restrict__ gH,     // [960, 18]
                  float* __restrict__ gout)         // [B, 18]
{
    __shared__ __align__(16) float s_xA[120 * SR];  // 8160 fl; reused as scratch in epilogue
    __shared__ __align__(16) float s_ac[120 * 8];   // act[m][c]
    __shared__ __align__(16) float s_W[480];
    __shared__ float s_apart[120];                  // per-warp a_sum partials [w][c]
    __shared__ float s_q1p[120];
    __shared__ float s_q2p[16];
    __shared__ float s_msc[18];                     // [0..7]=asum,[8..15]=rc,[16]=rg,[17]=sc2
    __shared__ float s_bias[8];

    const int tid  = threadIdx.x;
    const int b    = blockIdx.x;
    const int g    = tid >> 6;            // 0..7 (g-pure warps)
    const int f    = tid & 63;            // active when < 60
    const int vt   = g * 60 + f;          // flat index 0..479 when active
    const int w    = tid >> 5;
    const int lane = tid & 31;
    const bool actv = (f < 60);

    if (tid < 480) s_W[tid] = gW[tid];
    if (tid < 8)   s_bias[tid] = gbias[tid];

    const float* xb = gx + (size_t)b * (Mdim * Fdim);

    u64 c1[4], c2[4];
#pragma unroll
    for (int p = 0; p < 4; p++) { c1[p] = 0ULL; c2[p] = 0ULL; }
    float asr0 = 0.f, asr1 = 0.f;         // phase-A a_sum register partials

    const int am = tid >> 2;              // phase-A row 0..119 (tid<480)
    const int aj = tid & 3;               // phase-A k-quarter (interleaved)

    for (int ch = 0; ch < 5; ++ch) {
        // ---- load chunk: registers (phase B) + row-major smem tile (phase A) ----
        float st[15];
        if (actv) {
            const float* src = xb + ch * 7200 + vt;    // = x[(g+8i)*60 + f]
#pragma unroll
            for (int i = 0; i < 15; i++) st[i] = src[480 * i];
            float* dst = &s_xA[g * SR + f];
#pragma unroll
            for (int i = 0; i < 15; i++) dst[i * 8 * SR] = st[i];
        }
        __syncthreads();

        // ---- phase A: act = softmax(x@W + bias); thread = (row am, quarter aj) ----
        if (tid < 480) {
            u64 aa0 = 0, aa1 = 0, aa2 = 0, aa3 = 0;
            const float* xp = &s_xA[am * SR + aj];
#pragma unroll
            for (int kq = 0; kq < 15; kq++) {
                int kk = aj + 4 * kq;                  // interleaved k
                float xk = xp[4 * kq];
                u64 xx = pk2(xk, xk);
                const ulonglong2* wp = (const ulonglong2*)&s_W[kk * 8];
                ulonglong2 wA = wp[0], wB = wp[1];
                aa0 = ffma2(xx, wA.x, aa0);
                aa1 = ffma2(xx, wA.y, aa1);
                aa2 = ffma2(xx, wB.x, aa2);
                aa3 = ffma2(xx, wB.y, aa3);
            }
            aa0 = fadd2(aa0, __shfl_xor_sync(0xffffffffu, aa0, 1));
            aa1 = fadd2(aa1, __shfl_xor_sync(0xffffffffu, aa1, 1));
            aa2 = fadd2(aa2, __shfl_xor_sync(0xffffffffu, aa2, 1));
            aa3 = fadd2(aa3, __shfl_xor_sync(0xffffffffu, aa3, 1));
            aa0 = fadd2(aa0, __shfl_xor_sync(0xffffffffu, aa0, 2));
            aa1 = fadd2(aa1, __shfl_xor_sync(0xffffffffu, aa1, 2));
            aa2 = fadd2(aa2, __shfl_xor_sync(0xffffffffu, aa2, 2));
            aa3 = fadd2(aa3, __shfl_xor_sync(0xffffffffu, aa3, 2));
            float2 p0 = upk2(aa0), p1 = upk2(aa1), p2 = upk2(aa2), p3 = upk2(aa3);
            p0.x += s_bias[0]; p0.y += s_bias[1];
            p1.x += s_bias[2]; p1.y += s_bias[3];
            p2.x += s_bias[4]; p2.y += s_bias[5];
            p3.x += s_bias[6]; p3.y += s_bias[7];
            float mx = fmaxf(fmaxf(fmaxf(p0.x, p0.y), fmaxf(p1.x, p1.y)),
                             fmaxf(fmaxf(p2.x, p2.y), fmaxf(p3.x, p3.y)));
            float2 mp = (aj < 2) ? ((aj == 0) ? p0 : p1) : ((aj == 2) ? p2 : p3);
            float e0 = __expf(mp.x - mx);
            float e1 = __expf(mp.y - mx);
            float s2 = e0 + e1;
            s2 += __shfl_xor_sync(0xffffffffu, s2, 1);
            s2 += __shfl_xor_sync(0xffffffffu, s2, 2);
            float inv = __fdividef(1.f, s2);
            float v0 = e0 * inv, v1 = e1 * inv;
            *(float2*)&s_ac[am * 8 + 2 * aj] = make_float2(v0, v1);
            asr0 += v0; asr1 += v1;        // reduced once after the chunk loop
        }
        __syncthreads();

        // ---- phase B: fv1/fv2; x from registers, act via warp-broadcast LDS ----
        if (actv) {
#pragma unroll
            for (int i = 0; i < 15; i++) {
                int m = g + 8 * i;
                ulonglong2 A01 = *(const ulonglong2*)&s_ac[m * 8];
                ulonglong2 A23 = *(const ulonglong2*)&s_ac[m * 8 + 4];
                float xv = st[i];
                u64 xx = pk2(xv, xv);
                float xs = xv * xv;
                u64 xq = pk2(xs, xs);
                c1[0] = ffma2(A01.x, xx, c1[0]);  c2[0] = ffma2(A01.x, xq, c2[0]);
                c1[1] = ffma2(A01.y, xx, c1[1]);  c2[1] = ffma2(A01.y, xq, c2[1]);
                c1[2] = ffma2(A23.x, xx, c1[2]);  c2[2] = ffma2(A23.x, xq, c2[2]);
                c1[3] = ffma2(A23.y, xx, c1[3]);  c2[3] = ffma2(A23.y, xq, c2[3]);
            }
        }
        __syncthreads();
    }

    // ================= epilogue =================
    float* s_red = s_xA;            // 3840
    float* s_fv  = s_xA + 3840;     // 960
    float* s_pt  = s_xA + 4800;     // 486

    // a_sum: reduce register partials (rows within warp: xor 4,8,16)
    if (tid < 480) {
        float r0 = asr0, r1 = asr1;
        r0 += __shfl_xor_sync(0xffffffffu, r0, 4);
        r1 += __shfl_xor_sync(0xffffffffu, r1, 4);
        r0 += __shfl_xor_sync(0xffffffffu, r0, 8);
        r1 += __shfl_xor_sync(0xffffffffu, r1, 8);
        r0 += __shfl_xor_sync(0xffffffffu, r0, 16);
        r1 += __shfl_xor_sync(0xffffffffu, r1, 16);
        if (lane < 4) {
            s_apart[w * 8 + 2 * aj]     = r0;
            s_apart[w * 8 + 2 * aj + 1] = r1;
        }
    }
    // dump acc1 per (g,f)
    if (actv) {
        float2 q0 = upk2(c1[0]), q1 = upk2(c1[1]), q2v = upk2(c1[2]), q3 = upk2(c1[3]);
        float4* rp = (float4*)&s_red[vt * 8];
        rp[0] = make_float4(q0.x, q0.y, q1.x, q1.y);
        rp[1] = make_float4(q2v.x, q2v.y, q3.x, q3.y);
    }
    __syncthreads();
    if (tid < 8) {
        float A = 0.f;
#pragma unroll
        for (int ww = 0; ww < 15; ww++) A += s_apart[ww * 8 + tid];
        s_msc[tid] = A;
    }
    float fv1raw = 0.f, fv2raw = 0.f;
    if (tid < 480) {
#pragma unroll
        for (int gg = 0; gg < 8; gg++) fv1raw += s_red[gg * 480 + tid];
    }
    __syncthreads();
    if (actv) {
        float2 q0 = upk2(c2[0]), q1 = upk2(c2[1]), q2v = upk2(c2[2]), q3 = upk2(c2[3]);
        float4* rp = (float4*)&s_red[vt * 8];
        rp[0] = make_float4(q0.x, q0.y, q1.x, q1.y);
        rp[1] = make_float4(q2v.x, q2v.y, q3.x, q3.y);
    }
    __syncthreads();

    float fv1 = 0.f, fv2 = 0.f;
    if (tid < 480) {
#pragma unroll
        for (int gg = 0; gg < 8; gg++) fv2raw += s_red[gg * 480 + tid];
        const int c2i = tid & 7;
        float Asum = s_msc[c2i];
        float w2v  = gw2[tid];
        float cv   = gcov[tid];
        float cw   = cv * cv + 1e-6f;
        fv1 = (fv1raw - Asum * w2v) / cw;
        fv2 = (Asum * w2v * w2v + fv2raw - 2.f * fv1raw * w2v) / (cw * cw) - Asum;

        float sq1 = fv1 * fv1;
        float sq2 = fv2 * fv2;
        sq1 += __shfl_xor_sync(0xffffffffu, sq1, 8);
        sq1 += __shfl_xor_sync(0xffffffffu, sq1, 16);
        sq2 += __shfl_xor_sync(0xffffffffu, sq2, 1);
        sq2 += __shfl_xor_sync(0xffffffffu, sq2, 2);
        sq2 += __shfl_xor_sync(0xffffffffu, sq2, 4);
        sq2 += __shfl_xor_sync(0xffffffffu, sq2, 8);
        sq2 += __shfl_xor_sync(0xffffffffu, sq2, 16);
        if (lane < 8)  s_q1p[w * 8 + lane] = sq1;
        if (lane == 0) s_q2p[w] = sq2;
    }
    __syncthreads();
    if (tid == 0) {
        float G = 0.f;
#pragma unroll
        for (int c = 0; c < 8; c++) {
            float q = 0.f;
#pragma unroll
            for (int ww = 0; ww < 15; ww++) q += s_q1p[ww * 8 + c];
            float r = rsqrtf(fmaxf(q, 1e-12f));
            s_msc[8 + c] = r;
            G += q * r * r;
        }
        s_msc[16] = rsqrtf(fmaxf(G, 1e-12f));
        float q2s = 0.f;
#pragma unroll
        for (int ww = 0; ww < 15; ww++) q2s += s_q2p[ww];
        float r2  = rsqrtf(fmaxf(q2s, 1e-12f));
        float q2b = q2s * r2 * r2;
        s_msc[17] = r2 * rsqrtf(fmaxf(q2b, 1e-12f));
    }
    __syncthreads();
    if (tid < 480) {
        s_fv[tid]       = fv1 * s_msc[8 + (tid & 7)] * s_msc[16];
        s_fv[480 + tid] = fv2 * s_msc[17];
    }
    __syncthreads();

    // final matvec: out[b,:] = fv(960) @ H(960x18)
    if (tid < 486) {
        int ggq = tid / 18;
        int o   = tid - ggq * 18;
        float acc = 0.f;
        for (int jj = ggq; jj < 960; jj += 27)
            acc += s_fv[jj] * gH[jj * 18 + o];
        s_pt[tid] = acc;
    }
    __syncthreads();
    if (tid < 18) {
        float s = 0.f;
#pragma unroll
        for (int ggq = 0; ggq < 27; ggq++) s += s_pt[ggq * 18 + tid];
        gout[b * OUTd + tid] = s;
    }
}

extern "C" void kernel_launch(void* const* d_in, const int* in_sizes, int n_in,
                              void* d_out, int out_size) {
    const float* x    = (const float*)d_in[0];
    const float* W    = (const float*)d_in[1];
    const float* cov  = (const float*)d_in[2];
    const float* bias = (const float*)d_in[3];
    const float* w2   = (const float*)d_in[4];
    const float* H    = (const float*)d_in[5];
    float* out = (float*)d_out;

    int B = in_sizes[0] / (Mdim * Fdim);   // 2048
    netfv_kernel<<<B, NTHR>>>(x, W, cov, bias, w2, H, out);
}